// round 1
// baseline (speedup 1.0000x reference)
#include <cuda_runtime.h>
#include <math.h>

#define NN 4096
#define DD 256
#define CAP 2048   // compacted-support capacity per row

// ---------------- device scratch (static allocs are allowed) ----------------
__device__ float g_negT[(size_t)NN * NN];   // -cost^T
__device__ float g_tau_col[NN];
__device__ float g_beta[(size_t)NN * DD];
__device__ float g_alpha[(size_t)NN * DD];
__device__ float g_v1[DD];
__device__ float g_v2[DD];
__device__ float g_y;

// ---------------- reduction helpers ----------------
__device__ __forceinline__ float warpRedSum(float v) {
#pragma unroll
    for (int o = 16; o > 0; o >>= 1) v += __shfl_xor_sync(0xffffffffu, v, o);
    return v;
}

// sum across 256 threads, broadcast result to all
__device__ __forceinline__ float blockReduceSum(float v, float* red, int tid) {
    v = warpRedSum(v);
    if ((tid & 31) == 0) red[tid >> 5] = v;
    __syncthreads();
    if (tid == 0) {
        float s = 0.f;
#pragma unroll
        for (int i = 0; i < 8; i++) s += red[i];
        red[32] = s;
    }
    __syncthreads();
    float r = red[32];
    __syncthreads();
    return r;
}

// simultaneous (sum, count) reduce + broadcast
__device__ __forceinline__ void blockReduce2(float& a, float& b, float* red, int tid) {
    a = warpRedSum(a);
    b = warpRedSum(b);
    if ((tid & 31) == 0) { red[tid >> 5] = a; red[8 + (tid >> 5)] = b; }
    __syncthreads();
    if (tid == 0) {
        float s = 0.f, c = 0.f;
#pragma unroll
        for (int i = 0; i < 8; i++) { s += red[i]; c += red[8 + i]; }
        red[32] = s; red[33] = c;
    }
    __syncthreads();
    a = red[32];
    b = red[33];
    __syncthreads();
}

// exclusive scan of per-thread counts over 256 threads; returns thread's offset
__device__ __forceinline__ int blockScanExcl(int cnt, int& total, int tid) {
    __shared__ int warp_tot[8];
    const unsigned mask = 0xffffffffu;
    int lane = tid & 31, w = tid >> 5;
    int incl = cnt;
#pragma unroll
    for (int o = 1; o < 32; o <<= 1) {
        int n = __shfl_up_sync(mask, incl, o);
        if (lane >= o) incl += n;
    }
    if (lane == 31) warp_tot[w] = incl;
    __syncthreads();
    if (w == 0) {
        int t = (lane < 8) ? warp_tot[lane] : 0;
#pragma unroll
        for (int o = 1; o < 8; o <<= 1) {
            int n = __shfl_up_sync(mask, t, o);
            if (lane >= o) t += n;
        }
        if (lane < 8) warp_tot[lane] = t;   // inclusive warp totals
    }
    __syncthreads();
    int warp_off = (w == 0) ? 0 : warp_tot[w - 1];
    total = warp_tot[7];
    __syncthreads();
    return warp_off + incl - cnt;
}

// ---------------- sparsemax core (Michelot iteration) + sparse mix ----------------
// xrow: NN floats (optionally negated on load). Computes tau, optionally writes
// alignment row, stores tau, and accumulates mix_out[row, :] = sum_j p_j * V[j, :].
__device__ __forceinline__ void spmax_core(const float* __restrict__ xrow, bool negate,
                                           float* __restrict__ align_row,
                                           float* __restrict__ tau_store,
                                           const float* __restrict__ V,
                                           float* __restrict__ mix_out, int row) {
    __shared__ float xs[NN];        // 16 KB row cache
    __shared__ float red[40];
    __shared__ int   s_idx[CAP];    // compacted support indices
    int tid = threadIdx.x;          // 256 threads

    // load (+ optional negate) and running sum
    float lsum = 0.f;
#pragma unroll
    for (int j = tid * 4; j < NN; j += 256 * 4) {
        float4 v = *(const float4*)(xrow + j);
        if (negate) { v.x = -v.x; v.y = -v.y; v.z = -v.z; v.w = -v.w; }
        *(float4*)(xs + j) = v;
        lsum += (v.x + v.y) + (v.z + v.w);
    }
    __syncthreads();

    float total = blockReduceSum(lsum, red, tid);
    float tau = (total - 1.0f) * (1.0f / NN);
    int kprev = NN;

    // Michelot: support shrinks monotonically; exact fixed point = sparsemax tau
    for (int it = 0; it < 64; ++it) {
        float ls = 0.f, lc = 0.f;
        for (int j = tid; j < NN; j += 256) {
            float x = xs[j];
            if (x > tau) { ls += x; lc += 1.0f; }
        }
        blockReduce2(ls, lc, red, tid);
        int k = (int)lc;
        if (k == kprev) break;
        tau = (ls - 1.0f) / (float)k;
        kprev = k;
    }

    // write alignment row (coalesced)
    if (align_row) {
#pragma unroll
        for (int j = tid * 4; j < NN; j += 256 * 4) {
            float4 v = *(const float4*)(xs + j);
            float4 o;
            o.x = fmaxf(v.x - tau, 0.f);
            o.y = fmaxf(v.y - tau, 0.f);
            o.z = fmaxf(v.z - tau, 0.f);
            o.w = fmaxf(v.w - tau, 0.f);
            *(float4*)(align_row + j) = o;
        }
    }
    if (tau_store && tid == 0) *tau_store = tau;

    // deterministic compaction of support indices
    int cnt = 0;
    for (int j = tid; j < NN; j += 256)
        if (xs[j] > tau) cnt++;
    int nnz;
    int base = blockScanExcl(cnt, nnz, tid);
    if (nnz <= CAP) {
        int pos = base;
        for (int j = tid; j < NN; j += 256)
            if (xs[j] > tau) s_idx[pos++] = j;
    }
    __syncthreads();

    // mix: out[row, d] = sum_{j in support} (xs[j]-tau) * V[j, d], d = tid
    float acc = 0.f;
    if (nnz <= CAP) {
        for (int n = 0; n < nnz; n++) {
            int j = s_idx[n];
            acc = fmaf(xs[j] - tau, V[(size_t)j * DD + tid], acc);
        }
    } else {
        for (int j = 0; j < NN; j++) {
            float p = xs[j] - tau;
            if (p > 0.f) acc = fmaf(p, V[(size_t)j * DD + tid], acc);
        }
    }
    mix_out[(size_t)row * DD + tid] = acc;
}

// ---------------- kernels ----------------
__global__ void zero_kernel() {
    int t = threadIdx.x;
    g_v1[t] = 0.f;
    g_v2[t] = 0.f;
}

__global__ void transpose_neg_kernel(const float* __restrict__ in) {
    __shared__ float t[32][33];
    int bx = blockIdx.x * 32, by = blockIdx.y * 32;
    int tx = threadIdx.x, ty = threadIdx.y;
#pragma unroll
    for (int dy = 0; dy < 32; dy += 8)
        t[ty + dy][tx] = -in[(size_t)(by + ty + dy) * NN + bx + tx];
    __syncthreads();
#pragma unroll
    for (int dy = 0; dy < 32; dy += 8)
        g_negT[(size_t)(bx + ty + dy) * NN + by + tx] = t[tx][ty + dy];
}

__global__ __launch_bounds__(256) void spmax_row_kernel(const float* __restrict__ cost,
                                                        float* __restrict__ a0,
                                                        const float* __restrict__ colvecs) {
    int row = blockIdx.x;
    spmax_core(cost + (size_t)row * NN, true, a0 + (size_t)row * NN, nullptr,
               colvecs, g_beta, row);
}

__global__ __launch_bounds__(256) void spmax_col_kernel(const float* __restrict__ rowvecs) {
    int row = blockIdx.x;   // = column index of original cost
    spmax_core(g_negT + (size_t)row * NN, false, nullptr, &g_tau_col[row],
               rowvecs, g_alpha, row);
}

// align1[i, j] = max(-cost[i,j] - tau_col[j], 0), coalesced
__global__ void col_align_kernel(const float* __restrict__ cost, float* __restrict__ out) {
    size_t idx = ((size_t)blockIdx.x * blockDim.x + threadIdx.x) * 4;
    int j = (int)(idx & (NN - 1));
    float4 c = *(const float4*)(cost + idx);
    float4 o;
    o.x = fmaxf(-c.x - g_tau_col[j + 0], 0.f);
    o.y = fmaxf(-c.y - g_tau_col[j + 1], 0.f);
    o.z = fmaxf(-c.z - g_tau_col[j + 2], 0.f);
    o.w = fmaxf(-c.w - g_tau_col[j + 3], 0.f);
    *(float4*)(out + idx) = o;
}

// partial sums of leaky_relu(X @ W + b) over 16 rows per block
__global__ __launch_bounds__(256) void g_mean_kernel(const float* __restrict__ Wg,
                                                     const float* __restrict__ bg,
                                                     int which) {
    const float* Xall = which ? g_alpha : g_beta;
    float* gv = which ? g_v2 : g_v1;
    __shared__ float xs[16 * 256];
    int tid = threadIdx.x;
    size_t r0 = (size_t)blockIdx.x * 16;
#pragma unroll
    for (int r = 0; r < 16; r++) xs[r * 256 + tid] = Xall[(r0 + r) * 256 + tid];
    __syncthreads();

    float acc[16];
#pragma unroll
    for (int r = 0; r < 16; r++) acc[r] = 0.f;
#pragma unroll 4
    for (int k = 0; k < 256; k++) {
        float w = Wg[k * 256 + tid];
#pragma unroll
        for (int r = 0; r < 16; r++) acc[r] = fmaf(xs[r * 256 + k], w, acc[r]);
    }
    float bb = bg[tid], s = 0.f;
#pragma unroll
    for (int r = 0; r < 16; r++) {
        float z = acc[r] + bb;
        s += (z > 0.f) ? z : 0.2f * z;   // leaky_relu slope 0.2
    }
    atomicAdd(&gv[tid], s);
}

__global__ void cosine_kernel() {
    __shared__ float red[40];
    int tid = threadIdx.x;  // 256
    float v1 = g_v1[tid] * (1.0f / NN);
    float v2 = g_v2[tid] * (1.0f / NN);
    float d = v1 * v2, a = v1 * v1, b = v2 * v2;
    d = blockReduceSum(d, red, tid);
    a = blockReduceSum(a, red, tid);
    b = blockReduceSum(b, red, tid);
    if (tid == 0)
        g_y = 1.0f - d / (sqrtf(a) * sqrtf(b) + 1e-8f);
}

__global__ void fill_kernel(float* __restrict__ out) {
    float y = g_y;
    size_t idx = ((size_t)blockIdx.x * blockDim.x + threadIdx.x) * 4;
    float4 v = make_float4(y, y, y, y);
    *(float4*)(out + idx) = v;
}

// ---------------- launch ----------------
extern "C" void kernel_launch(void* const* d_in, const int* in_sizes, int n_in,
                              void* d_out, int out_size) {
    const float* row_vecs    = (const float*)d_in[0];   // [4096, 256]
    const float* column_vecs = (const float*)d_in[1];   // [4096, 256]
    const float* cost        = (const float*)d_in[2];   // [4096, 4096]
    const float* W_G         = (const float*)d_in[3];   // [256, 256]
    const float* b_G         = (const float*)d_in[4];   // [256]

    float* out      = (float*)d_out;
    float* cost_out = out;                               // [4096, 4096]  = y
    float* a0       = out + (size_t)NN * NN;             // row_alignment
    float* a1       = out + 2 * (size_t)NN * NN;         // column_alignment

    (void)in_sizes; (void)n_in; (void)out_size;

    zero_kernel<<<1, 256>>>();
    transpose_neg_kernel<<<dim3(NN / 32, NN / 32), dim3(32, 8)>>>(cost);
    spmax_row_kernel<<<NN, 256>>>(cost, a0, column_vecs);
    spmax_col_kernel<<<NN, 256>>>(row_vecs);
    col_align_kernel<<<(NN * (size_t)NN) / (4 * 256), 256>>>(cost, a1);
    g_mean_kernel<<<NN / 16, 256>>>(W_G, b_G, 0);
    g_mean_kernel<<<NN / 16, 256>>>(W_G, b_G, 1);
    cosine_kernel<<<1, 256>>>();
    fill_kernel<<<(NN * (size_t)NN) / (4 * 256), 256>>>(cost_out);
}